// round 3
// baseline (speedup 1.0000x reference)
#include <cuda_runtime.h>
#include <math.h>

#define NN 100000
#define FD 512
#define HD 16
#define CD 40
#define EMAX 3400000

// ---------------- scratch (device globals; no allocation allowed) ----------
__device__ int g_is64;
__device__ __align__(16) int    g_src [EMAX];
__device__ __align__(16) int    g_dst [EMAX];
__device__ __align__(16) float  g_deg [NN];
__device__ __align__(16) float  g_dinv[NN];
__device__ __align__(16) float4 g_h1s [NN * 4];   // h1 * dinv[row], 16 floats/row
__device__ __align__(16) float4 g_acc1[NN * 4];   // sum over in-edges (incl self loop)
__device__ __align__(16) float4 g_h2s [NN * 10];  // h2 * dinv[row], 40 floats/row
__device__ __align__(16) float4 g_acc2[NN * 10];

// 128-bit global reduction (no return) — REDG.128
__device__ __forceinline__ void red4(float4* p, float4 v) {
    asm volatile("red.global.add.v4.f32 [%0], {%1,%2,%3,%4};"
                 :: "l"(p), "f"(v.x), "f"(v.y), "f"(v.z), "f"(v.w)
                 : "memory");
}

// ---------------- K-1: detect edge-index dtype ------------------------------
// int64 data (values < 2^31): odd int32 words are all zero.
// int32 data: odd words are random node ids (never all zero over 256 samples).
__global__ void k_detect(const int* __restrict__ buf) {
    int nz = 0;
    for (int i = threadIdx.x; i < 256; i += 32) nz |= buf[2 * i + 1];
#pragma unroll
    for (int o = 16; o; o >>= 1) nz |= __shfl_xor_sync(0xffffffffu, nz, o);
    if (threadIdx.x == 0) g_is64 = (nz == 0) ? 1 : 0;
}

// ---------------- K0: unpack edges to int32; reset degree -------------------
__global__ void k_convert(const void* __restrict__ buf, int E) {
    int e = blockIdx.x * blockDim.x + threadIdx.x;
    if (e < NN) g_deg[e] = 1.0f;           // self-loop pre-count
    if (e >= E) return;
    if (g_is64) {
        const long long* p = (const long long*)buf;
        g_src[e] = (int)p[e];
        g_dst[e] = (int)p[e + E];
    } else {
        const int* p = (const int*)buf;
        g_src[e] = p[e];
        g_dst[e] = p[e + E];
    }
}

// ---------------- K1: in-degree histogram over dst --------------------------
__global__ void k_deg(int E) {
    int e = blockIdx.x * blockDim.x + threadIdx.x;
    if (e < E) atomicAdd(&g_deg[g_dst[e]], 1.0f);
}

// ---------------- K2: h1s = (x @ W1) * dinv ; acc1 = h1s (self loop) --------
__global__ void __launch_bounds__(128) k_gemm1(const float* __restrict__ x,
                                               const float* __restrict__ W1) {
    __shared__ float4 wt4[HD][FD / 4];   // W1 transposed, float4 along k: 32KB
    int t = threadIdx.x;
    for (int i = t; i < HD * (FD / 4); i += 128) {
        int c  = i / (FD / 4);
        int k4 = i % (FD / 4);
        wt4[c][k4] = make_float4(W1[(4 * k4 + 0) * HD + c],
                                 W1[(4 * k4 + 1) * HD + c],
                                 W1[(4 * k4 + 2) * HD + c],
                                 W1[(4 * k4 + 3) * HD + c]);
    }
    __syncthreads();

    int r = blockIdx.x * 128 + t;
    if (r >= NN) return;

    const float4* xr = (const float4*)(x + (size_t)r * FD);
    float acc[HD];
#pragma unroll
    for (int c = 0; c < HD; c++) acc[c] = 0.0f;

#pragma unroll 2
    for (int k4 = 0; k4 < FD / 4; k4++) {
        float4 xv = __ldg(xr + k4);
#pragma unroll
        for (int c = 0; c < HD; c++) {
            float4 wv = wt4[c][k4];
            acc[c] = fmaf(xv.x, wv.x,
                     fmaf(xv.y, wv.y,
                     fmaf(xv.z, wv.z,
                     fmaf(xv.w, wv.w, acc[c]))));
        }
    }

    float dv = rsqrtf(g_deg[r]);
    g_dinv[r] = dv;
    float4* h1 = g_h1s  + r * 4;
    float4* a1 = g_acc1 + r * 4;
#pragma unroll
    for (int q = 0; q < 4; q++) {
        float4 v = make_float4(acc[4 * q + 0] * dv, acc[4 * q + 1] * dv,
                               acc[4 * q + 2] * dv, acc[4 * q + 3] * dv);
        h1[q] = v;
        a1[q] = v;
    }
}

// ---------------- K3: edge scatter-add, layer 1 (16 floats/edge) ------------
__global__ void k_agg1(int E) {
    int e = blockIdx.x * blockDim.x + threadIdx.x;
    if (e >= E) return;
    int s = g_src[e];
    int d = g_dst[e];
    const float4* hs = g_h1s  + s * 4;
    float4*       ad = g_acc1 + d * 4;
#pragma unroll
    for (int q = 0; q < 4; q++) red4(ad + q, __ldg(hs + q));
}

// ---------------- K4: out1 = dinv*acc1 + b1; relu; h2s=(t@W2)*dinv ----------
__global__ void __launch_bounds__(128) k_layer2(const float* __restrict__ W2,
                                                const float* __restrict__ b1) {
    __shared__ float4 w2s[HD][CD / 4];   // 16 x 10 float4
    __shared__ float  b1s[HD];
    int t = threadIdx.x;
    for (int i = t; i < HD * (CD / 4); i += 128) {
        int k = i / (CD / 4);
        int j = i % (CD / 4);
        w2s[k][j] = __ldg((const float4*)(W2 + k * CD) + j);
    }
    if (t < HD) b1s[t] = b1[t];
    __syncthreads();

    int r = blockIdx.x * 128 + t;
    if (r >= NN) return;

    float dv = g_dinv[r];
    const float4* a1 = g_acc1 + r * 4;
    float tt[HD];
#pragma unroll
    for (int q = 0; q < 4; q++) {
        float4 v = a1[q];
        tt[4 * q + 0] = fmaxf(fmaf(v.x, dv, b1s[4 * q + 0]), 0.0f);
        tt[4 * q + 1] = fmaxf(fmaf(v.y, dv, b1s[4 * q + 1]), 0.0f);
        tt[4 * q + 2] = fmaxf(fmaf(v.z, dv, b1s[4 * q + 2]), 0.0f);
        tt[4 * q + 3] = fmaxf(fmaf(v.w, dv, b1s[4 * q + 3]), 0.0f);
    }

    float acc[CD];
#pragma unroll
    for (int c = 0; c < CD; c++) acc[c] = 0.0f;
#pragma unroll
    for (int k = 0; k < HD; k++) {
        float tv = tt[k];
#pragma unroll
        for (int j = 0; j < CD / 4; j++) {
            float4 w = w2s[k][j];
            acc[4 * j + 0] = fmaf(tv, w.x, acc[4 * j + 0]);
            acc[4 * j + 1] = fmaf(tv, w.y, acc[4 * j + 1]);
            acc[4 * j + 2] = fmaf(tv, w.z, acc[4 * j + 2]);
            acc[4 * j + 3] = fmaf(tv, w.w, acc[4 * j + 3]);
        }
    }

    float4* h2 = g_h2s  + r * 10;
    float4* a2 = g_acc2 + r * 10;
#pragma unroll
    for (int j = 0; j < CD / 4; j++) {
        float4 v = make_float4(acc[4 * j + 0] * dv, acc[4 * j + 1] * dv,
                               acc[4 * j + 2] * dv, acc[4 * j + 3] * dv);
        h2[j] = v;
        a2[j] = v;
    }
}

// ---------------- K5: edge scatter-add, layer 2 (40 floats/edge) ------------
__global__ void k_agg2(int E) {
    int e = blockIdx.x * blockDim.x + threadIdx.x;
    if (e >= E) return;
    int s = g_src[e];
    int d = g_dst[e];
    const float4* hs = g_h2s  + s * 10;
    float4*       ad = g_acc2 + d * 10;
#pragma unroll
    for (int j = 0; j < CD / 4; j++) red4(ad + j, __ldg(hs + j));
}

// ---------------- K6: logits = dinv*acc2 + b2 ; log_softmax -----------------
__global__ void __launch_bounds__(128) k_final(const float* __restrict__ b2,
                                               float* __restrict__ out,
                                               int write_logits) {
    __shared__ float b2s[CD];
    int t = threadIdx.x;
    if (t < CD) b2s[t] = b2[t];
    __syncthreads();

    int r = blockIdx.x * 128 + t;
    if (r >= NN) return;

    float dv = g_dinv[r];
    const float4* a2 = g_acc2 + r * 10;
    float l[CD];
#pragma unroll
    for (int j = 0; j < CD / 4; j++) {
        float4 v = a2[j];
        l[4 * j + 0] = fmaf(v.x, dv, b2s[4 * j + 0]);
        l[4 * j + 1] = fmaf(v.y, dv, b2s[4 * j + 1]);
        l[4 * j + 2] = fmaf(v.z, dv, b2s[4 * j + 2]);
        l[4 * j + 3] = fmaf(v.w, dv, b2s[4 * j + 3]);
    }

    float m = -1e30f;
#pragma unroll
    for (int c = 0; c < CD; c++) m = fmaxf(m, l[c]);
    float sum = 0.0f;
#pragma unroll
    for (int c = 0; c < CD; c++) sum += expf(l[c] - m);
    float lse = m + logf(sum);

    float4* o1 = (float4*)(out + (size_t)r * CD);
#pragma unroll
    for (int j = 0; j < CD / 4; j++) {
        o1[j] = make_float4(l[4 * j + 0] - lse, l[4 * j + 1] - lse,
                            l[4 * j + 2] - lse, l[4 * j + 3] - lse);
    }
    if (write_logits) {
        float4* o2 = (float4*)(out + (size_t)NN * CD + (size_t)r * CD);
#pragma unroll
        for (int j = 0; j < CD / 4; j++)
            o2[j] = make_float4(l[4 * j + 0], l[4 * j + 1],
                                l[4 * j + 2], l[4 * j + 3]);
    }
}

// ---------------- host ------------------------------------------------------
extern "C" void kernel_launch(void* const* d_in, const int* in_sizes, int n_in,
                              void* d_out, int out_size) {
    const float* x   = (const float*)d_in[0];
    const void*  ei  = (const void*)d_in[1];
    const float* W1  = (const float*)d_in[2];
    const float* b1  = (const float*)d_in[3];
    const float* W2  = (const float*)d_in[4];
    const float* b2  = (const float*)d_in[5];
    float*       out = (float*)d_out;

    int E = in_sizes[1] / 2;          // element count is 2*E for either dtype
    if (E > EMAX) E = EMAX;

    int write_logits = (out_size >= 2 * NN * CD) ? 1 : 0;

    int nb_node128 = (NN + 127) / 128;
    int nb_edge    = (E + 255) / 256;

    k_detect<<<1, 32>>>((const int*)ei);
    k_convert<<<nb_edge, 256>>>(ei, E);
    k_deg<<<nb_edge, 256>>>(E);
    k_gemm1<<<nb_node128, 128>>>(x, W1);
    k_agg1<<<nb_edge, 256>>>(E);
    k_layer2<<<nb_node128, 128>>>(W2, b1);
    k_agg2<<<nb_edge, 256>>>(E);
    k_final<<<nb_node128, 128>>>(b2, out, write_logits);
}

// round 5
// speedup vs baseline: 1.5937x; 1.5937x over previous
#include <cuda_runtime.h>
#include <math.h>

#define NN 100000
#define FD 512
#define HD 16
#define CD 40
#define EMAX 3400000

// ---------------- scratch (device globals; no allocation allowed) ----------
__device__ int g_is64;
__device__ __align__(16) int    g_src [EMAX];
__device__ __align__(16) int    g_dst [EMAX];
__device__ __align__(16) float  g_deg [NN];
__device__ __align__(16) float  g_dinv[NN];
__device__ __align__(16) float4 g_h1s [NN * 4];   // (x@W1)*dinv   : 16 f/row
__device__ __align__(16) float4 g_acc1[NN * 4];   // layer-1 accum : 16 f/row
__device__ __align__(16) float4 g_ts  [NN * 4];   // relu(out1)*dinv : 16 f/row
__device__ __align__(16) float4 g_acc2[NN * 4];   // layer-2 accum : 16 f/row

// 128-bit global reduction (no return) — REDG.128
__device__ __forceinline__ void red4(float4* p, float4 v) {
    asm volatile("red.global.add.v4.f32 [%0], {%1,%2,%3,%4};"
                 :: "l"(p), "f"(v.x), "f"(v.y), "f"(v.z), "f"(v.w)
                 : "memory");
}

// packed fp32x2 helpers (Blackwell FFMA2 — PTX only)
__device__ __forceinline__ unsigned long long pk2(float a, float b) {
    unsigned long long r;
    asm("mov.b64 %0, {%1, %2};" : "=l"(r) : "f"(a), "f"(b));
    return r;
}
__device__ __forceinline__ void fma2(unsigned long long& d,
                                     unsigned long long a, unsigned long long b) {
    asm("fma.rn.f32x2 %0, %1, %2, %0;" : "+l"(d) : "l"(a), "l"(b));
}
__device__ __forceinline__ float unpk_sum(unsigned long long v) {
    float lo, hi;
    asm("mov.b64 {%0, %1}, %2;" : "=f"(lo), "=f"(hi) : "l"(v));
    return lo + hi;
}

// ---------------- K-1: detect edge-index dtype ------------------------------
__global__ void k_detect(const int* __restrict__ buf) {
    int nz = 0;
    for (int i = threadIdx.x; i < 256; i += 32) nz |= buf[2 * i + 1];
#pragma unroll
    for (int o = 16; o; o >>= 1) nz |= __shfl_xor_sync(0xffffffffu, nz, o);
    if (threadIdx.x == 0) g_is64 = (nz == 0) ? 1 : 0;
}

// ---------------- K0a: deg = 1 (self loop) ----------------------------------
__global__ void k_init() {
    int i = blockIdx.x * blockDim.x + threadIdx.x;
    if (i < NN) g_deg[i] = 1.0f;
}

// ---------------- K0b: unpack edges to int32 + degree histogram -------------
__global__ void k_convert(const void* __restrict__ buf, int E) {
    int e = blockIdx.x * blockDim.x + threadIdx.x;
    if (e >= E) return;
    int s, d;
    if (g_is64) {
        const long long* p = (const long long*)buf;
        s = (int)p[e];
        d = (int)p[e + E];
    } else {
        const int* p = (const int*)buf;
        s = p[e];
        d = p[e + E];
    }
    g_src[e] = s;
    g_dst[e] = d;
    atomicAdd(&g_deg[d], 1.0f);
}

// ---------------- K1: h1s = (x @ W1) * dinv ; acc1 = h1s (self loop) --------
// 128 threads, 2 rows/thread, 256 rows/block. W1 pre-packed in smem as
// k-pair ulonglong2: wp[k2][c2] = {(W[2k2][2c2],W[2k2+1][2c2]),
//                                  (W[2k2][2c2+1],W[2k2+1][2c2+1])}
__global__ void __launch_bounds__(128) k_gemm1(const float* __restrict__ x,
                                               const float* __restrict__ W1) {
    __shared__ ulonglong2 wp[FD / 2][HD / 2];   // 256 x 8 x 16B = 32KB
    int t = threadIdx.x;
    for (int i = t; i < (FD / 2) * (HD / 2); i += 128) {
        int k2 = i / (HD / 2);
        int c2 = i % (HD / 2);
        ulonglong2 v;
        v.x = pk2(W1[(2 * k2) * HD + 2 * c2],     W1[(2 * k2 + 1) * HD + 2 * c2]);
        v.y = pk2(W1[(2 * k2) * HD + 2 * c2 + 1], W1[(2 * k2 + 1) * HD + 2 * c2 + 1]);
        wp[k2][c2] = v;
    }
    __syncthreads();

    int r0 = blockIdx.x * 256 + t;
    int r1 = r0 + 128;
    if (r0 >= NN) return;
    bool has1 = (r1 < NN);
    if (!has1) r1 = r0;   // safe alias

    const ulonglong2* xr0 = (const ulonglong2*)(x + (size_t)r0 * FD);
    const ulonglong2* xr1 = (const ulonglong2*)(x + (size_t)r1 * FD);

    unsigned long long accA[HD], accB[HD];
#pragma unroll
    for (int c = 0; c < HD; c++) { accA[c] = 0ull; accB[c] = 0ull; }

    // 512 floats/row = 128 ulonglong2; batch 4 per row per iter (64B each)
    for (int it = 0; it < 32; ++it) {
        ulonglong2 a[4], b[4];
#pragma unroll
        for (int m = 0; m < 4; m++) {
            a[m] = __ldg(xr0 + 4 * it + m);
            b[m] = __ldg(xr1 + 4 * it + m);
        }
#pragma unroll
        for (int m = 0; m < 4; m++) {
            int k2 = it * 8 + 2 * m;       // a[m].x covers k-pair k2, .y covers k2+1
#pragma unroll
            for (int c2 = 0; c2 < HD / 2; c2++) {
                ulonglong2 wv = wp[k2][c2];
                fma2(accA[2 * c2 + 0], a[m].x, wv.x);
                fma2(accA[2 * c2 + 1], a[m].x, wv.y);
                fma2(accB[2 * c2 + 0], b[m].x, wv.x);
                fma2(accB[2 * c2 + 1], b[m].x, wv.y);
            }
#pragma unroll
            for (int c2 = 0; c2 < HD / 2; c2++) {
                ulonglong2 wv = wp[k2 + 1][c2];
                fma2(accA[2 * c2 + 0], a[m].y, wv.x);
                fma2(accA[2 * c2 + 1], a[m].y, wv.y);
                fma2(accB[2 * c2 + 0], b[m].y, wv.x);
                fma2(accB[2 * c2 + 1], b[m].y, wv.y);
            }
        }
    }

    {
        float dv = rsqrtf(g_deg[r0]);
        g_dinv[r0] = dv;
        float4* h1 = g_h1s  + r0 * 4;
        float4* a1 = g_acc1 + r0 * 4;
#pragma unroll
        for (int q = 0; q < 4; q++) {
            float4 v = make_float4(unpk_sum(accA[4 * q + 0]) * dv,
                                   unpk_sum(accA[4 * q + 1]) * dv,
                                   unpk_sum(accA[4 * q + 2]) * dv,
                                   unpk_sum(accA[4 * q + 3]) * dv);
            h1[q] = v; a1[q] = v;
        }
    }
    if (has1) {
        float dv = rsqrtf(g_deg[r1]);
        g_dinv[r1] = dv;
        float4* h1 = g_h1s  + r1 * 4;
        float4* a1 = g_acc1 + r1 * 4;
#pragma unroll
        for (int q = 0; q < 4; q++) {
            float4 v = make_float4(unpk_sum(accB[4 * q + 0]) * dv,
                                   unpk_sum(accB[4 * q + 1]) * dv,
                                   unpk_sum(accB[4 * q + 2]) * dv,
                                   unpk_sum(accB[4 * q + 3]) * dv);
            h1[q] = v; a1[q] = v;
        }
    }
}

// ---------------- K2: edge scatter-add layer 1 (16 floats/edge) -------------
__global__ void k_agg1(int E) {
    int e = blockIdx.x * blockDim.x + threadIdx.x;
    if (e >= E) return;
    int s = g_src[e];
    int d = g_dst[e];
    const float4* hs = g_h1s  + s * 4;
    float4*       ad = g_acc1 + d * 4;
#pragma unroll
    for (int q = 0; q < 4; q++) red4(ad + q, __ldg(hs + q));
}

// ---------------- K3: ts = relu(dinv*acc1 + b1) * dinv ; acc2 = ts ----------
__global__ void __launch_bounds__(256) k_mid(const float* __restrict__ b1) {
    __shared__ float b1s[HD];
    int t = threadIdx.x;
    if (t < HD) b1s[t] = b1[t];
    __syncthreads();

    int r = blockIdx.x * 256 + t;
    if (r >= NN) return;

    float dv = g_dinv[r];
    const float4* a1 = g_acc1 + r * 4;
    float4* ts = g_ts   + r * 4;
    float4* a2 = g_acc2 + r * 4;
#pragma unroll
    for (int q = 0; q < 4; q++) {
        float4 v = a1[q];
        float4 o;
        o.x = fmaxf(fmaf(v.x, dv, b1s[4 * q + 0]), 0.0f) * dv;
        o.y = fmaxf(fmaf(v.y, dv, b1s[4 * q + 1]), 0.0f) * dv;
        o.z = fmaxf(fmaf(v.z, dv, b1s[4 * q + 2]), 0.0f) * dv;
        o.w = fmaxf(fmaf(v.w, dv, b1s[4 * q + 3]), 0.0f) * dv;
        ts[q] = o; a2[q] = o;
    }
}

// ---------------- K4: edge scatter-add layer 2 (16 floats/edge) -------------
__global__ void k_agg2(int E) {
    int e = blockIdx.x * blockDim.x + threadIdx.x;
    if (e >= E) return;
    int s = g_src[e];
    int d = g_dst[e];
    const float4* hs = g_ts   + s * 4;
    float4*       ad = g_acc2 + d * 4;
#pragma unroll
    for (int q = 0; q < 4; q++) red4(ad + q, __ldg(hs + q));
}

// ---------------- K5: logits = (dinv*acc2)@W2 + b2 ; log_softmax ------------
__global__ void __launch_bounds__(256) k_final(const float* __restrict__ W2,
                                               const float* __restrict__ b2,
                                               float* __restrict__ out,
                                               int write_logits) {
    __shared__ float4 w2s[HD][CD / 4];   // 16 x 10 float4 = 2.5KB
    __shared__ float  b2s[CD];
    int t = threadIdx.x;
    for (int i = t; i < HD * (CD / 4); i += 256) {
        int k = i / (CD / 4);
        int j = i % (CD / 4);
        w2s[k][j] = __ldg((const float4*)(W2 + k * CD) + j);
    }
    if (t < CD) b2s[t] = b2[t];
    __syncthreads();

    int r = blockIdx.x * 256 + t;
    if (r >= NN) return;

    float dv = g_dinv[r];
    const float4* a2 = g_acc2 + r * 4;
    float z[HD];
#pragma unroll
    for (int q = 0; q < 4; q++) {
        float4 v = a2[q];
        z[4 * q + 0] = v.x * dv;
        z[4 * q + 1] = v.y * dv;
        z[4 * q + 2] = v.z * dv;
        z[4 * q + 3] = v.w * dv;
    }

    float l[CD];
#pragma unroll
    for (int c = 0; c < CD; c++) l[c] = b2s[c];
#pragma unroll
    for (int k = 0; k < HD; k++) {
        float zv = z[k];
#pragma unroll
        for (int j = 0; j < CD / 4; j++) {
            float4 w = w2s[k][j];
            l[4 * j + 0] = fmaf(zv, w.x, l[4 * j + 0]);
            l[4 * j + 1] = fmaf(zv, w.y, l[4 * j + 1]);
            l[4 * j + 2] = fmaf(zv, w.z, l[4 * j + 2]);
            l[4 * j + 3] = fmaf(zv, w.w, l[4 * j + 3]);
        }
    }

    float m = -1e30f;
#pragma unroll
    for (int c = 0; c < CD; c++) m = fmaxf(m, l[c]);
    float sum = 0.0f;
#pragma unroll
    for (int c = 0; c < CD; c++) sum += expf(l[c] - m);
    float lse = m + logf(sum);

    float4* o1 = (float4*)(out + (size_t)r * CD);
#pragma unroll
    for (int j = 0; j < CD / 4; j++)
        o1[j] = make_float4(l[4 * j + 0] - lse, l[4 * j + 1] - lse,
                            l[4 * j + 2] - lse, l[4 * j + 3] - lse);
    if (write_logits) {
        float4* o2 = (float4*)(out + (size_t)NN * CD + (size_t)r * CD);
#pragma unroll
        for (int j = 0; j < CD / 4; j++)
            o2[j] = make_float4(l[4 * j + 0], l[4 * j + 1],
                                l[4 * j + 2], l[4 * j + 3]);
    }
}

// ---------------- host ------------------------------------------------------
extern "C" void kernel_launch(void* const* d_in, const int* in_sizes, int n_in,
                              void* d_out, int out_size) {
    const float* x   = (const float*)d_in[0];
    const void*  ei  = (const void*)d_in[1];
    const float* W1  = (const float*)d_in[2];
    const float* b1  = (const float*)d_in[3];
    const float* W2  = (const float*)d_in[4];
    const float* b2  = (const float*)d_in[5];
    float*       out = (float*)d_out;

    int E = in_sizes[1] / 2;
    if (E > EMAX) E = EMAX;

    int write_logits = (out_size >= 2 * NN * CD) ? 1 : 0;

    int nb_node256 = (NN + 255) / 256;
    int nb_gemm    = (NN + 255) / 256;   // 256 rows / block, 128 threads
    int nb_edge    = (E + 255) / 256;

    k_detect<<<1, 32>>>((const int*)ei);
    k_init<<<nb_node256, 256>>>();
    k_convert<<<nb_edge, 256>>>(ei, E);
    k_gemm1<<<nb_gemm, 128>>>(x, W1);
    k_agg1<<<nb_edge, 256>>>(E);
    k_mid<<<nb_node256, 256>>>(b1);
    k_agg2<<<nb_edge, 256>>>(E);
    k_final<<<nb_node256, 256>>>(W2, b2, out, write_logits);
}

// round 7
// speedup vs baseline: 1.9056x; 1.1957x over previous
#include <cuda_runtime.h>
#include <math.h>

#define NN 100000
#define FD 512
#define HD 16
#define CD 40
#define EMAX 3400000
#define NB_NODE 391   // ceil(NN/256)

// ---------------- scratch (device globals; no allocation allowed) ----------
__device__ int g_is64;
__device__ __align__(16) int    g_cnt   [NN];     // in-degree (excl self)
__device__ __align__(16) int    g_start [NN];     // CSR row start
__device__ __align__(16) int    g_cursor[NN];
__device__ __align__(16) int    g_bsum  [512];
__device__ __align__(16) int    g_src [EMAX];
__device__ __align__(16) int    g_dst [EMAX];
__device__ __align__(16) int    g_csr [EMAX];     // src ids grouped by dst
__device__ __align__(16) float  g_dinv[NN];
__device__ __align__(16) float4 g_h1s [NN * 4];   // (x@W1)*dinv
__device__ __align__(16) float4 g_ts  [NN * 4];   // relu(out1)*dinv
__device__ __align__(16) float4 g_acc2[NN * 4];   // layer-2 aggregate (raw)

// packed fp32x2 helpers (Blackwell FFMA2 — PTX only)
__device__ __forceinline__ unsigned long long pk2(float a, float b) {
    unsigned long long r;
    asm("mov.b64 %0, {%1, %2};" : "=l"(r) : "f"(a), "f"(b));
    return r;
}
__device__ __forceinline__ void fma2(unsigned long long& d,
                                     unsigned long long a, unsigned long long b) {
    asm("fma.rn.f32x2 %0, %1, %2, %0;" : "+l"(d) : "l"(a), "l"(b));
}
__device__ __forceinline__ float unpk_sum(unsigned long long v) {
    float lo, hi;
    asm("mov.b64 {%0, %1}, %2;" : "=f"(lo), "=f"(hi) : "l"(v));
    return lo + hi;
}

// ---------------- K: detect edge-index dtype --------------------------------
__global__ void k_detect(const int* __restrict__ buf) {
    int nz = 0;
    for (int i = threadIdx.x; i < 256; i += 32) nz |= buf[2 * i + 1];
#pragma unroll
    for (int o = 16; o; o >>= 1) nz |= __shfl_xor_sync(0xffffffffu, nz, o);
    if (threadIdx.x == 0) g_is64 = (nz == 0) ? 1 : 0;
}

// ---------------- K: zero counters ------------------------------------------
__global__ void k_init() {
    int i = blockIdx.x * blockDim.x + threadIdx.x;
    if (i < NN) { g_cnt[i] = 0; g_cursor[i] = 0; }
}

// ---------------- K: decode edges + degree histogram ------------------------
__global__ void k_count(const void* __restrict__ buf, int E) {
    int e = blockIdx.x * blockDim.x + threadIdx.x;
    if (e >= E) return;
    int s, d;
    if (g_is64) {
        const long long* p = (const long long*)buf;
        s = (int)p[e]; d = (int)p[e + E];
    } else {
        const int* p = (const int*)buf;
        s = p[e]; d = p[e + E];
    }
    g_src[e] = s;
    g_dst[e] = d;
    atomicAdd(&g_cnt[d], 1);
}

// ---------------- K: CSR prefix sum (3 steps) -------------------------------
__global__ void k_scanA() {
    __shared__ int sh[256];
    int i = blockIdx.x * 256 + threadIdx.x;
    sh[threadIdx.x] = (i < NN) ? g_cnt[i] : 0;
    __syncthreads();
    for (int s = 128; s; s >>= 1) {
        if (threadIdx.x < s) sh[threadIdx.x] += sh[threadIdx.x + s];
        __syncthreads();
    }
    if (threadIdx.x == 0) g_bsum[blockIdx.x] = sh[0];
}
__global__ void k_scanB(int nb) {
    __shared__ int sh[512];
    int t = threadIdx.x;
    int v = (t < nb) ? g_bsum[t] : 0;
    sh[t] = v;
    __syncthreads();
    for (int off = 1; off < 512; off <<= 1) {
        int a = (t >= off) ? sh[t - off] : 0;
        __syncthreads();
        sh[t] += a;
        __syncthreads();
    }
    if (t < nb) g_bsum[t] = sh[t] - v;   // exclusive
}
__global__ void k_scanC() {
    __shared__ int sh[256];
    int i = blockIdx.x * 256 + threadIdx.x;
    int t = threadIdx.x;
    int v = (i < NN) ? g_cnt[i] : 0;
    sh[t] = v;
    __syncthreads();
    for (int off = 1; off < 256; off <<= 1) {
        int a = (t >= off) ? sh[t - off] : 0;
        __syncthreads();
        sh[t] += a;
        __syncthreads();
    }
    if (i < NN) g_start[i] = sh[t] - v + g_bsum[blockIdx.x];
}

// ---------------- K: fill CSR (group src by dst) ----------------------------
__global__ void k_fill(int E) {
    int e = blockIdx.x * blockDim.x + threadIdx.x;
    if (e >= E) return;
    int s = g_src[e];
    int d = g_dst[e];
    int pos = atomicAdd(&g_cursor[d], 1);
    g_csr[g_start[d] + pos] = s;
}

// ---------------- K: h1s = (x @ W1) * dinv ----------------------------------
// 256 threads, 1 row/thread. W1 pre-packed in smem as k-pair ulonglong2.
__global__ void __launch_bounds__(256) k_gemm1(const float* __restrict__ x,
                                               const float* __restrict__ W1) {
    __shared__ ulonglong2 wp[FD / 2][HD / 2];   // 32KB
    int t = threadIdx.x;
    for (int i = t; i < (FD / 2) * (HD / 2); i += 256) {
        int k2 = i / (HD / 2);
        int c2 = i % (HD / 2);
        ulonglong2 v;
        v.x = pk2(W1[(2 * k2) * HD + 2 * c2],     W1[(2 * k2 + 1) * HD + 2 * c2]);
        v.y = pk2(W1[(2 * k2) * HD + 2 * c2 + 1], W1[(2 * k2 + 1) * HD + 2 * c2 + 1]);
        wp[k2][c2] = v;
    }
    __syncthreads();

    int r = blockIdx.x * 256 + t;
    if (r >= NN) return;

    const ulonglong2* xr = (const ulonglong2*)(x + (size_t)r * FD);
    unsigned long long acc[HD];
#pragma unroll
    for (int c = 0; c < HD; c++) acc[c] = 0ull;

    for (int it = 0; it < 32; ++it) {
        ulonglong2 a[4];
#pragma unroll
        for (int m = 0; m < 4; m++) a[m] = __ldg(xr + 4 * it + m);
#pragma unroll
        for (int m = 0; m < 4; m++) {
            int k2 = it * 8 + 2 * m;
#pragma unroll
            for (int c2 = 0; c2 < HD / 2; c2++) {
                ulonglong2 wv = wp[k2][c2];
                fma2(acc[2 * c2 + 0], a[m].x, wv.x);
                fma2(acc[2 * c2 + 1], a[m].x, wv.y);
            }
#pragma unroll
            for (int c2 = 0; c2 < HD / 2; c2++) {
                ulonglong2 wv = wp[k2 + 1][c2];
                fma2(acc[2 * c2 + 0], a[m].y, wv.x);
                fma2(acc[2 * c2 + 1], a[m].y, wv.y);
            }
        }
    }

    float dv = rsqrtf((float)g_cnt[r] + 1.0f);
    g_dinv[r] = dv;
    float4* h1 = g_h1s + r * 4;
#pragma unroll
    for (int q = 0; q < 4; q++)
        h1[q] = make_float4(unpk_sum(acc[4 * q + 0]) * dv,
                            unpk_sum(acc[4 * q + 1]) * dv,
                            unpk_sum(acc[4 * q + 2]) * dv,
                            unpk_sum(acc[4 * q + 3]) * dv);
}

// ---------------- K: gather layer 1 + fused mid -----------------------------
// Warp per node; lane = (neighbor-slot n = lane>>2, quad q = lane&3).
__global__ void __launch_bounds__(256) k_gather1(const float* __restrict__ b1) {
    int gw   = (blockIdx.x * 256 + threadIdx.x) >> 5;   // node
    int lane = threadIdx.x & 31;
    if (gw >= NN) return;
    int q = lane & 3, n = lane >> 2;
    int beg = g_start[gw], cnt = g_cnt[gw];

    float4 acc = make_float4(0.f, 0.f, 0.f, 0.f);
    for (int i = n; i < cnt; i += 8) {
        int s = __ldg(g_csr + beg + i);
        float4 h = __ldg(g_h1s + s * 4 + q);
        acc.x += h.x; acc.y += h.y; acc.z += h.z; acc.w += h.w;
    }
#pragma unroll
    for (int off = 16; off >= 4; off >>= 1) {
        acc.x += __shfl_xor_sync(0xffffffffu, acc.x, off);
        acc.y += __shfl_xor_sync(0xffffffffu, acc.y, off);
        acc.z += __shfl_xor_sync(0xffffffffu, acc.z, off);
        acc.w += __shfl_xor_sync(0xffffffffu, acc.w, off);
    }
    if (lane < 4) {
        float4 self = g_h1s[gw * 4 + q];
        float  dv   = g_dinv[gw];
        float4 bb   = __ldg((const float4*)b1 + q);
        float4 o;
        o.x = fmaxf(fmaf(acc.x + self.x, dv, bb.x), 0.f) * dv;
        o.y = fmaxf(fmaf(acc.y + self.y, dv, bb.y), 0.f) * dv;
        o.z = fmaxf(fmaf(acc.z + self.z, dv, bb.z), 0.f) * dv;
        o.w = fmaxf(fmaf(acc.w + self.w, dv, bb.w), 0.f) * dv;
        g_ts[gw * 4 + q] = o;
    }
}

// ---------------- K: gather layer 2 -----------------------------------------
__global__ void __launch_bounds__(256) k_gather2() {
    int gw   = (blockIdx.x * 256 + threadIdx.x) >> 5;
    int lane = threadIdx.x & 31;
    if (gw >= NN) return;
    int q = lane & 3, n = lane >> 2;
    int beg = g_start[gw], cnt = g_cnt[gw];

    float4 acc = make_float4(0.f, 0.f, 0.f, 0.f);
    for (int i = n; i < cnt; i += 8) {
        int s = __ldg(g_csr + beg + i);
        float4 h = __ldg(g_ts + s * 4 + q);
        acc.x += h.x; acc.y += h.y; acc.z += h.z; acc.w += h.w;
    }
#pragma unroll
    for (int off = 16; off >= 4; off >>= 1) {
        acc.x += __shfl_xor_sync(0xffffffffu, acc.x, off);
        acc.y += __shfl_xor_sync(0xffffffffu, acc.y, off);
        acc.z += __shfl_xor_sync(0xffffffffu, acc.z, off);
        acc.w += __shfl_xor_sync(0xffffffffu, acc.w, off);
    }
    if (lane < 4) {
        float4 self = g_ts[gw * 4 + q];
        g_acc2[gw * 4 + q] = make_float4(acc.x + self.x, acc.y + self.y,
                                         acc.z + self.z, acc.w + self.w);
    }
}

// ---------------- K: logits = (dinv*acc2)@W2 + b2 ; log_softmax -------------
__global__ void __launch_bounds__(256) k_final(const float* __restrict__ W2,
                                               const float* __restrict__ b2,
                                               float* __restrict__ out,
                                               int write_logits) {
    __shared__ float4 w2s[HD][CD / 4];
    __shared__ float  b2s[CD];
    int t = threadIdx.x;
    for (int i = t; i < HD * (CD / 4); i += 256) {
        int k = i / (CD / 4);
        int j = i % (CD / 4);
        w2s[k][j] = __ldg((const float4*)(W2 + k * CD) + j);
    }
    if (t < CD) b2s[t] = b2[t];
    __syncthreads();

    int r = blockIdx.x * 256 + t;
    if (r >= NN) return;

    float dv = g_dinv[r];
    const float4* a2 = g_acc2 + r * 4;
    float z[HD];
#pragma unroll
    for (int qq = 0; qq < 4; qq++) {
        float4 v = a2[qq];
        z[4 * qq + 0] = v.x * dv;
        z[4 * qq + 1] = v.y * dv;
        z[4 * qq + 2] = v.z * dv;
        z[4 * qq + 3] = v.w * dv;
    }

    float l[CD];
#pragma unroll
    for (int c = 0; c < CD; c++) l[c] = b2s[c];
#pragma unroll
    for (int k = 0; k < HD; k++) {
        float zv = z[k];
#pragma unroll
        for (int j = 0; j < CD / 4; j++) {
            float4 w = w2s[k][j];
            l[4 * j + 0] = fmaf(zv, w.x, l[4 * j + 0]);
            l[4 * j + 1] = fmaf(zv, w.y, l[4 * j + 1]);
            l[4 * j + 2] = fmaf(zv, w.z, l[4 * j + 2]);
            l[4 * j + 3] = fmaf(zv, w.w, l[4 * j + 3]);
        }
    }

    float m = -1e30f;
#pragma unroll
    for (int c = 0; c < CD; c++) m = fmaxf(m, l[c]);
    float sum = 0.0f;
#pragma unroll
    for (int c = 0; c < CD; c++) sum += expf(l[c] - m);
    float lse = m + logf(sum);

    float4* o1 = (float4*)(out + (size_t)r * CD);
#pragma unroll
    for (int j = 0; j < CD / 4; j++)
        o1[j] = make_float4(l[4 * j + 0] - lse, l[4 * j + 1] - lse,
                            l[4 * j + 2] - lse, l[4 * j + 3] - lse);
    if (write_logits) {
        float4* o2 = (float4*)(out + (size_t)NN * CD + (size_t)r * CD);
#pragma unroll
        for (int j = 0; j < CD / 4; j++)
            o2[j] = make_float4(l[4 * j + 0], l[4 * j + 1],
                                l[4 * j + 2], l[4 * j + 3]);
    }
}

// ---------------- host ------------------------------------------------------
extern "C" void kernel_launch(void* const* d_in, const int* in_sizes, int n_in,
                              void* d_out, int out_size) {
    const float* x   = (const float*)d_in[0];
    const void*  ei  = (const void*)d_in[1];
    const float* W1  = (const float*)d_in[2];
    const float* b1  = (const float*)d_in[3];
    const float* W2  = (const float*)d_in[4];
    const float* b2  = (const float*)d_in[5];
    float*       out = (float*)d_out;

    int E = in_sizes[1] / 2;
    if (E > EMAX) E = EMAX;

    int write_logits = (out_size >= 2 * NN * CD) ? 1 : 0;
    int nb_edge   = (E + 255) / 256;
    int nb_gather = (NN * 32 + 255) / 256;   // warp per node

    k_detect<<<1, 32>>>((const int*)ei);
    k_init<<<NB_NODE, 256>>>();
    k_count<<<nb_edge, 256>>>(ei, E);
    k_scanA<<<NB_NODE, 256>>>();
    k_scanB<<<1, 512>>>(NB_NODE);
    k_scanC<<<NB_NODE, 256>>>();
    k_fill<<<nb_edge, 256>>>(E);
    k_gemm1<<<NB_NODE, 256>>>(x, W1);
    k_gather1<<<nb_gather, 256>>>(b1);
    k_gather2<<<nb_gather, 256>>>();
    k_final<<<NB_NODE, 256>>>(W2, b2, out, write_logits);
}